// round 14
// baseline (speedup 1.0000x reference)
#include <cuda_runtime.h>
#include <math.h>

#define DD 512
#define NN 128
#define TB 8

typedef unsigned long long ull;

__device__ float g_picked[NN];

// ---- packed f32x2 helpers (Blackwell FFMA2 path, PTX-only) -----------------
static __device__ __forceinline__ ull ffma2(ull a, ull b, ull c)
{
    ull d;
    asm("fma.rn.f32x2 %0, %1, %2, %3;" : "=l"(d) : "l"(a), "l"(b), "l"(c));
    return d;
}
static __device__ __forceinline__ ull pack2(float x, float y)
{
    ull d;
    asm("mov.b64 %0, {%1, %2};" : "=l"(d) : "f"(x), "f"(y));
    return d;
}
static __device__ __forceinline__ void unpack2(ull v, float& x, float& y)
{
    asm("mov.b64 {%0, %1}, %2;" : "=f"(x), "=f"(y) : "l"(v));
}

// ---------------------------------------------------------------------------
// TWO independent chains per CTA (512 threads): warps 0-7 process output row
// k = blockIdx.x, warps 8-15 process k + 64. Each chain is the validated R11
// kernel: Omega (128x128) register-resident, 2 rows x 32 interleaved cols per
// thread; per TB=8-site block: phase1 dot + butterfly -> gram -> redundant
// warp-local 8x8 LU -> fwdsub in regs -> rank-8 update. Both chains walk the
// SAME site sequence i0=0,8,16,.. so they share pv_s and synchronize with
// common __syncthreads; between barriers each SMSP interleaves two
// independent dependency chains (latency hiding without extra instructions).
// ---------------------------------------------------------------------------
__global__ void __launch_bounds__(512, 1)
sampler_kernel(const float* __restrict__ P, const int* __restrict__ pos,
               float* __restrict__ out)
{
    __shared__ __align__(16) float pv_s[2][TB][NN];      // shared by chains
    __shared__ __align__(16) float wfin[2][TB][NN];      // per chain
    __shared__ __align__(16) float Y_s[2][TB][NN];       // per chain
    __shared__ __align__(16) float S_s[2][64];           // per chain
    __shared__ float rd_s[2][TB];                        // per chain
    __shared__ unsigned char occ[DD];                    // shared

    const int tid   = threadIdx.x;
    const int lane  = tid & 31;
    const int chain = tid >> 8;              // 0 or 1
    const int cwid  = (tid >> 5) & 7;        // warp index within chain
    const int rgl   = lane >> 2;             // 0..7
    const int cg    = lane & 3;              // 0..3
    const int r0    = cwid * 16 + rgl * 2;   // rows r0, r0+1

    const int k     = blockIdx.x + (chain << 6);

    if (tid < DD) occ[tid] = 0;
    __syncthreads();
    if (tid < NN) occ[pos[tid]] = 1;

    const int myPos = pos[k];
    const int xmin  = (k == 0) ? 0 : (pos[k - 1] + 1);
    const int xmax  = DD - NN + k + 1;
    const int xmax_hi = DD - NN + (blockIdx.x + 64) + 1;   // chain B bound

    {   // zero both output rows (each chain's 256 threads cover 512 entries)
        const int tl = tid & 255;
        out[k * DD + tl] = 0.0f;
        out[k * DD + tl + 256] = 0.0f;
    }

    // Omega = I. A2[rr][2q] covers (row r0+rr, cols 16q+4cg .. +3)
    ull A2[2][16];
#pragma unroll
    for (int rr = 0; rr < 2; rr++) {
        const int row = r0 + rr;
#pragma unroll
        for (int q = 0; q < 8; q++) {
            const int cb = 16 * q + 4 * cg;
            A2[rr][2 * q]     = pack2((row == cb)     ? 1.0f : 0.0f,
                                      (row == cb + 1) ? 1.0f : 0.0f);
            A2[rr][2 * q + 1] = pack2((row == cb + 2) ? 1.0f : 0.0f,
                                      (row == cb + 3) ? 1.0f : 0.0f);
        }
    }

    // stage first block's 8 P rows: 1024 floats = 256 float4 (chain-A threads)
    if (tid < 256) ((float4*)&pv_s[0][0][0])[tid] = __ldg((const float4*)P + tid);
    __syncthreads();

    float cprod = 1.0f;
    int buf = 0;
    for (int i0 = 0; i0 < xmax_hi; i0 += TB) {
        const bool lastg  = (i0 + TB >= xmax_hi);          // global last block
        const bool active = (i0 < xmax);                   // this chain active
        const bool lastc  = (i0 + TB >= xmax);             // chain's last block

        float4 pf;
        if (tid < 256 && !lastg)
            pf = __ldg((const float4*)(P + (i0 + TB) * NN) + tid);

        // ---- phase1: per b, 32-col partial dot for 2 rows + 2-stage butterfly
        float w0[TB], w1[TB];
        if (active) {
#pragma unroll
            for (int b = 0; b < TB; b++) {
                const ulonglong2* pb = (const ulonglong2*)&pv_s[buf][b][0];
                ull a00 = 0ull, a01 = 0ull, a10 = 0ull, a11 = 0ull;
#pragma unroll
                for (int q = 0; q < 8; q++) {
                    ulonglong2 u = pb[4 * q + cg];   // contig 64B x 4cg: 1 wavefront
                    a00 = ffma2(A2[0][2 * q],     u.x, a00);
                    a01 = ffma2(A2[0][2 * q + 1], u.y, a01);
                    a10 = ffma2(A2[1][2 * q],     u.x, a10);
                    a11 = ffma2(A2[1][2 * q + 1], u.y, a11);
                }
                float x0, y0, x1, y1;
                unpack2(a00, x0, y0); unpack2(a01, x1, y1);
                float s0 = (x0 + y0) + (x1 + y1);
                unpack2(a10, x0, y0); unpack2(a11, x1, y1);
                float s1 = (x0 + y0) + (x1 + y1);
                s0 += __shfl_xor_sync(0xffffffffu, s0, 1);
                s0 += __shfl_xor_sync(0xffffffffu, s0, 2);
                s1 += __shfl_xor_sync(0xffffffffu, s1, 1);
                s1 += __shfl_xor_sync(0xffffffffu, s1, 2);
                w0[b] = s0;
                w1[b] = s1;
                if (cg == 0) { wfin[chain][b][r0] = s0; wfin[chain][b][r0 + 1] = s1; }
            }
        }
        if (tid < 256 && !lastg)
            ((float4*)&pv_s[buf ^ 1][0][0])[tid] = pf;
        __syncthreads();                               // --- b1 ---

        // ---- Gram: warp 'cwid' computes S[cwid][b] = sum_r p_cwid[r]*w_b[r]
        if (active) {
            float4 pa = ((const float4*)&pv_s[buf][cwid][0])[lane];
            float sg[TB];
#pragma unroll
            for (int b = 0; b < TB; b++) {
                float4 wb4 = ((const float4*)&wfin[chain][b][0])[lane];
                sg[b] = pa.x * wb4.x + pa.y * wb4.y + pa.z * wb4.z + pa.w * wb4.w;
            }
#pragma unroll
            for (int off = 16; off; off >>= 1) {
#pragma unroll
                for (int b = 0; b < TB; b++)
                    sg[b] += __shfl_xor_sync(0xffffffffu, sg[b], off);
            }
            if (lane == 0) {
                *(float4*)&S_s[chain][cwid * 8]     = make_float4(sg[0], sg[1], sg[2], sg[3]);
                *(float4*)&S_s[chain][cwid * 8 + 4] = make_float4(sg[4], sg[5], sg[6], sg[7]);
            }
        }
        __syncthreads();                               // --- b2 ---

        // ---- redundant warp-local 8x8 LU on S; lane a<8 holds row a of S
        float Lcol[TB];
        if (active) {
            const int Teff = lastc ? (xmax - i0) : TB;
            float S_row[TB];
            if (lane < TB) {
                float4 s0v = *(const float4*)&S_s[chain][lane * 8];
                float4 s1v = *(const float4*)&S_s[chain][lane * 8 + 4];
                S_row[0] = s0v.x; S_row[1] = s0v.y; S_row[2] = s0v.z; S_row[3] = s0v.w;
                S_row[4] = s1v.x; S_row[5] = s1v.y; S_row[6] = s1v.z; S_row[7] = s1v.w;
            } else {
#pragma unroll
                for (int b = 0; b < TB; b++) S_row[b] = 0.0f;
            }
            float cp = cprod;
#pragma unroll
            for (int j = 0; j < TB; j++) {
                if (j >= Teff) break;
                float rj[TB];
#pragma unroll
                for (int b = 0; b < TB; b++)
                    rj[b] = __shfl_sync(0xffffffffu, S_row[b], j);
                const float beta = rj[j];
                const int i = i0 + j;
                const bool inwin = (i >= xmin);
                if (cwid == 0 && lane == 0 && inwin) {
                    float prob = cp * beta;
                    float pcl = (fabsf(prob) > 1e-15f) ? prob : 0.0f;
                    out[k * DD + i] = pcl;
                    if (i == myPos) g_picked[k] = pcl;
                }
                if (inwin) cp *= (1.0f - beta);
                if (i == xmax - 1) break;  // forced last site: no elimination
                const float d  = (!inwin && occ[i]) ? beta : (beta - 1.0f);
                const float rd = __fdividef(1.0f, d);
                if (cwid == 0 && lane == 0) rd_s[chain][j] = rd;
                const float mult = S_row[j] * rd;   // = L[lane][j] (symmetry)
                Lcol[j] = mult;
#pragma unroll
                for (int b = 0; b < TB; b++)
                    S_row[b] = fmaf(-mult, rj[b], S_row[b]);
            }
            cprod = cp;
        }

        // ---- forward substitution in registers (y aliases w0/w1)
        if (active && !lastc) {
#pragma unroll
            for (int j = 1; j < TB; j++) {
#pragma unroll
                for (int m = 0; m < j; m++) {
                    float ljm = __shfl_sync(0xffffffffu, Lcol[m], j);
                    w0[j] = fmaf(-ljm, w0[m], w0[j]);
                    w1[j] = fmaf(-ljm, w1[m], w1[j]);
                }
            }
            if (cg == 0) {
#pragma unroll
                for (int j = 0; j < TB; j++) {
                    Y_s[chain][j][r0]     = w0[j];
                    Y_s[chain][j][r0 + 1] = w1[j];
                }
            }
        }
        __syncthreads();                               // --- b3 ---

        // ---- rank-8 update: Omega[row][c] -= (y_j[row]*rd_j) * y_j[c]
        if (active && !lastc) {
#pragma unroll
            for (int j = 0; j < TB; j++) {
                const float rdj = rd_s[chain][j];
                const float z0 = -(w0[j] * rdj);
                const float z1 = -(w1[j] * rdj);
                const ull nz0 = pack2(z0, z0);
                const ull nz1 = pack2(z1, z1);
                const ulonglong2* yb = (const ulonglong2*)&Y_s[chain][j][0];
#pragma unroll
                for (int q = 0; q < 8; q++) {
                    ulonglong2 u = yb[4 * q + cg];
                    A2[0][2 * q]     = ffma2(nz0, u.x, A2[0][2 * q]);
                    A2[0][2 * q + 1] = ffma2(nz0, u.y, A2[0][2 * q + 1]);
                    A2[1][2 * q]     = ffma2(nz1, u.x, A2[1][2 * q]);
                    A2[1][2 * q + 1] = ffma2(nz1, u.y, A2[1][2 * q + 1]);
                }
            }
        }
        buf ^= 1;
    }
}

// ---------------------------------------------------------------------------
// Parallel log-sum of picked probabilities (one warp, tree reduction).
// ---------------------------------------------------------------------------
__global__ void logsum_kernel(float* __restrict__ out_scalar)
{
    int lane = threadIdx.x;
    float s = 0.0f;
    for (int k = lane; k < NN; k += 32) s += logf(g_picked[k]);
#pragma unroll
    for (int o = 16; o; o >>= 1) s += __shfl_xor_sync(0xffffffffu, s, o);
    if (lane == 0) *out_scalar = s;
}

extern "C" void kernel_launch(void* const* d_in, const int* in_sizes, int n_in,
                              void* d_out, int out_size)
{
    const float* P = (const float*)d_in[0];    // [D, N] float32
    const int* pos = (const int*)d_in[1];      // [N] int32, sorted
    float* out = (float*)d_out;                // [N*D probs][1 logprob]

    sampler_kernel<<<NN / 2, 512>>>(P, pos, out);
    logsum_kernel<<<1, 32>>>(out + (out_size - 1));
}

// round 15
// speedup vs baseline: 1.7845x; 1.7845x over previous
#include <cuda_runtime.h>
#include <math.h>

#define DD 512
#define NN 128
#define TB 8

typedef unsigned long long ull;

__device__ float g_picked[NN];

// ---- packed f32x2 helpers (Blackwell FFMA2 path, PTX-only) -----------------
static __device__ __forceinline__ ull ffma2(ull a, ull b, ull c)
{
    ull d;
    asm("fma.rn.f32x2 %0, %1, %2, %3;" : "=l"(d) : "l"(a), "l"(b), "l"(c));
    return d;
}
static __device__ __forceinline__ ull pack2(float x, float y)
{
    ull d;
    asm("mov.b64 %0, {%1, %2};" : "=l"(d) : "f"(x), "f"(y));
    return d;
}
static __device__ __forceinline__ void unpack2(ull v, float& x, float& y)
{
    asm("mov.b64 {%0, %1}, %2;" : "=f"(x), "=f"(y) : "l"(v));
}

// ---------------------------------------------------------------------------
// One CTA (256 threads, 8 warps) per output row k  (= best R11 layout).
// Omega (128x128) register-resident, 2 rows x 32 interleaved cols per thread:
//   warp w: rows [16w,16w+16); lane: rgl=lane>>2 -> rows r0=16w+2rgl, r0+1;
//   cg=lane&3 -> float4 chunks at cols 16q+4cg (q=0..7): the 4 cg groups of
//   one q are 64 contiguous bytes -> every broadcast LDS.128 = 1 wavefront.
// Per TB=8-site block:
//   FUSED pass: for each q-chunk, apply block n-1's rank-8 update to A2[q]
//     (z from regs, y cols from Y_s) then immediately dot A2[q] with the 8
//     current p rows -> one heavy interval, ~16 independent chains.  [b1]
//   gram:   S[a][b] = p_a . w_b (warp a, shfl tree)                  [b2]
//   LU:     redundant warp-local 8x8 LU (__fdividef); w0 lane0 emits probs
//   fwdsub: y_j in registers; publish Y_s; fold -rd into w (z)       [b3]
// ---------------------------------------------------------------------------
__global__ void __launch_bounds__(256, 1)
sampler_kernel(const float* __restrict__ P, const int* __restrict__ pos,
               float* __restrict__ out)
{
    __shared__ __align__(16) float pv_s[2][TB][NN];
    __shared__ __align__(16) float wfin[TB][NN];
    __shared__ __align__(16) float Y_s[TB][NN];
    __shared__ __align__(16) float S_s[64];
    __shared__ unsigned char occ[DD];

    const int k    = blockIdx.x;
    const int tid  = threadIdx.x;
    const int lane = tid & 31;
    const int wid  = tid >> 5;               // 0..7
    const int rgl  = lane >> 2;              // 0..7
    const int cg   = lane & 3;               // 0..3
    const int r0   = wid * 16 + rgl * 2;     // rows r0, r0+1

    for (int i = tid; i < DD; i += 256) occ[i] = 0;
    __syncthreads();
    if (tid < NN) occ[pos[tid]] = 1;

    const int myPos = pos[k];
    const int xmin  = (k == 0) ? 0 : (pos[k - 1] + 1);
    const int xmax  = DD - NN + k + 1;

    for (int i = tid; i < DD; i += 256) out[k * DD + i] = 0.0f;

    // Omega = I. A2[rr][2q] covers (row r0+rr, cols 16q+4cg .. +3)
    ull A2[2][16];
#pragma unroll
    for (int rr = 0; rr < 2; rr++) {
        const int row = r0 + rr;
#pragma unroll
        for (int q = 0; q < 8; q++) {
            const int cb = 16 * q + 4 * cg;
            A2[rr][2 * q]     = pack2((row == cb)     ? 1.0f : 0.0f,
                                      (row == cb + 1) ? 1.0f : 0.0f);
            A2[rr][2 * q + 1] = pack2((row == cb + 2) ? 1.0f : 0.0f,
                                      (row == cb + 3) ? 1.0f : 0.0f);
        }
    }

    // stage first block's 8 P rows: 1024 floats = 256 float4
    ((float4*)&pv_s[0][0][0])[tid] = __ldg((const float4*)P + tid);
    __syncthreads();

    float cprod = 1.0f;
    // After each block, w0/w1 hold z_j = -y_j[row]*rd_j (row side of update).
    float w0[TB], w1[TB];
    int buf = 0;
    bool doUpd = false;
    for (int i0 = 0; i0 < xmax; i0 += TB) {
        const bool last = (i0 + TB >= xmax);

        float4 pf;
        if (!last) pf = __ldg((const float4*)(P + (i0 + TB) * NN) + tid);

        // ---- FUSED pass: (apply prev block's rank-8 update) + dots, per q
        ull acc0[TB], acc1[TB];
#pragma unroll
        for (int b = 0; b < TB; b++) { acc0[b] = 0ull; acc1[b] = 0ull; }
        {
            const ulonglong2* pb = (const ulonglong2*)&pv_s[buf][0][0];
            const ulonglong2* yb = (const ulonglong2*)&Y_s[0][0];
            // rows of pv_s / Y_s are 128 floats = 32 ulonglong2
#pragma unroll
            for (int q = 0; q < 8; q++) {
                if (doUpd) {
#pragma unroll
                    for (int j = 0; j < TB; j++) {
                        ulonglong2 u = yb[j * 32 + 4 * q + cg];
                        ull nz0 = pack2(w0[j], w0[j]);
                        ull nz1 = pack2(w1[j], w1[j]);
                        A2[0][2 * q]     = ffma2(nz0, u.x, A2[0][2 * q]);
                        A2[0][2 * q + 1] = ffma2(nz0, u.y, A2[0][2 * q + 1]);
                        A2[1][2 * q]     = ffma2(nz1, u.x, A2[1][2 * q]);
                        A2[1][2 * q + 1] = ffma2(nz1, u.y, A2[1][2 * q + 1]);
                    }
                }
#pragma unroll
                for (int b = 0; b < TB; b++) {
                    ulonglong2 u = pb[b * 32 + 4 * q + cg];
                    acc0[b] = ffma2(A2[0][2 * q],     u.x, acc0[b]);
                    acc0[b] = ffma2(A2[0][2 * q + 1], u.y, acc0[b]);
                    acc1[b] = ffma2(A2[1][2 * q],     u.x, acc1[b]);
                    acc1[b] = ffma2(A2[1][2 * q + 1], u.y, acc1[b]);
                }
            }
        }
        // reduce accumulators -> full row dots (2-stage butterfly over 4 cgs)
#pragma unroll
        for (int b = 0; b < TB; b++) {
            float x0, y0, x1, y1;
            unpack2(acc0[b], x0, y0);
            float s0 = x0 + y0;
            unpack2(acc1[b], x1, y1);
            float s1 = x1 + y1;
            s0 += __shfl_xor_sync(0xffffffffu, s0, 1);
            s0 += __shfl_xor_sync(0xffffffffu, s0, 2);
            s1 += __shfl_xor_sync(0xffffffffu, s1, 1);
            s1 += __shfl_xor_sync(0xffffffffu, s1, 2);
            w0[b] = s0;
            w1[b] = s1;
            if (cg == 0) { wfin[b][r0] = s0; wfin[b][r0 + 1] = s1; }
        }
        if (!last) ((float4*)&pv_s[buf ^ 1][0][0])[tid] = pf;
        __syncthreads();                               // --- b1 ---

        // ---- Gram: warp 'wid' computes S[wid][b] = sum_r p_wid[r]*w_b[r]
        {
            float4 pa = ((const float4*)&pv_s[buf][wid][0])[lane];
            float sg[TB];
#pragma unroll
            for (int b = 0; b < TB; b++) {
                float4 wb4 = ((const float4*)&wfin[b][0])[lane];
                sg[b] = pa.x * wb4.x + pa.y * wb4.y + pa.z * wb4.z + pa.w * wb4.w;
            }
#pragma unroll
            for (int off = 16; off; off >>= 1) {
#pragma unroll
                for (int b = 0; b < TB; b++)
                    sg[b] += __shfl_xor_sync(0xffffffffu, sg[b], off);
            }
            if (lane == 0) {
                *(float4*)&S_s[wid * 8]     = make_float4(sg[0], sg[1], sg[2], sg[3]);
                *(float4*)&S_s[wid * 8 + 4] = make_float4(sg[4], sg[5], sg[6], sg[7]);
            }
        }
        __syncthreads();                               // --- b2 ---

        // ---- redundant warp-local 8x8 LU on S; lane a<8 holds row a of S
        const int Teff = last ? (xmax - i0) : TB;
        float S_row[TB];
        if (lane < TB) {
            float4 s0v = *(const float4*)&S_s[lane * 8];
            float4 s1v = *(const float4*)&S_s[lane * 8 + 4];
            S_row[0] = s0v.x; S_row[1] = s0v.y; S_row[2] = s0v.z; S_row[3] = s0v.w;
            S_row[4] = s1v.x; S_row[5] = s1v.y; S_row[6] = s1v.z; S_row[7] = s1v.w;
        } else {
#pragma unroll
            for (int b = 0; b < TB; b++) S_row[b] = 0.0f;
        }
        float Lcol[TB];
        float rdv[TB];
        float cp = cprod;
#pragma unroll
        for (int j = 0; j < TB; j++) {
            if (j >= Teff) break;
            float rj[TB];
#pragma unroll
            for (int b = 0; b < TB; b++)
                rj[b] = __shfl_sync(0xffffffffu, S_row[b], j);
            const float beta = rj[j];
            const int i = i0 + j;
            const bool inwin = (i >= xmin);
            if (wid == 0 && lane == 0 && inwin) {
                float prob = cp * beta;
                float pcl = (fabsf(prob) > 1e-15f) ? prob : 0.0f;
                out[k * DD + i] = pcl;
                if (i == myPos) g_picked[k] = pcl;
            }
            if (inwin) cp *= (1.0f - beta);
            if (i == xmax - 1) break;      // forced last site: no elimination
            const float d  = (!inwin && occ[i]) ? beta : (beta - 1.0f);
            const float rd = __fdividef(1.0f, d);
            rdv[j] = rd;
            const float mult = S_row[j] * rd;   // = L[lane][j] (symmetry)
            Lcol[j] = mult;
#pragma unroll
            for (int b = 0; b < TB; b++)
                S_row[b] = fmaf(-mult, rj[b], S_row[b]);
        }
        cprod = cp;
        if (last) break;

        // ---- forward substitution in registers (y aliases w0/w1):
        //      y_j = w_j - sum_{m<j} L[j][m] y_m (one shfl serves both rows)
#pragma unroll
        for (int j = 1; j < TB; j++) {
#pragma unroll
            for (int m = 0; m < j; m++) {
                float ljm = __shfl_sync(0xffffffffu, Lcol[m], j);
                w0[j] = fmaf(-ljm, w0[m], w0[j]);
                w1[j] = fmaf(-ljm, w1[m], w1[j]);
            }
        }
        if (cg == 0) {
#pragma unroll
            for (int j = 0; j < TB; j++) {
                Y_s[j][r0]     = w0[j];
                Y_s[j][r0 + 1] = w1[j];
            }
        }
        // fold -rd into w -> z (row side of next block's fused update)
#pragma unroll
        for (int j = 0; j < TB; j++) {
            w0[j] = -(w0[j] * rdv[j]);
            w1[j] = -(w1[j] * rdv[j]);
        }
        doUpd = true;
        __syncthreads();                               // --- b3 ---
        buf ^= 1;
    }
}

// ---------------------------------------------------------------------------
// Parallel log-sum of picked probabilities (one warp, tree reduction).
// ---------------------------------------------------------------------------
__global__ void logsum_kernel(float* __restrict__ out_scalar)
{
    int lane = threadIdx.x;
    float s = 0.0f;
    for (int k = lane; k < NN; k += 32) s += logf(g_picked[k]);
#pragma unroll
    for (int o = 16; o; o >>= 1) s += __shfl_xor_sync(0xffffffffu, s, o);
    if (lane == 0) *out_scalar = s;
}

extern "C" void kernel_launch(void* const* d_in, const int* in_sizes, int n_in,
                              void* d_out, int out_size)
{
    const float* P = (const float*)d_in[0];    // [D, N] float32
    const int* pos = (const int*)d_in[1];      // [N] int32, sorted
    float* out = (float*)d_out;                // [N*D probs][1 logprob]

    sampler_kernel<<<NN, 256>>>(P, pos, out);
    logsum_kernel<<<1, 32>>>(out + (out_size - 1));
}